// round 11
// baseline (speedup 1.0000x reference)
#include <cuda_runtime.h>
#include <cstdint>

// LIF recurrence: T=64 steps, B*N = 524288 independent lanes.
//   h = v + (x - v) * 0.5 ; s = (h>=1) ; v = s ? 0 : h
// Pure HBM stream: 134 MB in + 134 MB out (compulsory, zero reuse).
// ROOFLINE REACHED: seven structurally distinct schedules measured
// 47.4-48.7us harness = ~5.65 TB/s sustained mixed-stream HBM3e.
// Winning structure (R6/R10): distance-1 scalar prefetch, unroll 4,
// float4, plain LDG.128/STG.128, ~1024+ CTAs for even per-SM balance.
// R11 delta: CTA size 64 -> 2048 CTAs (13.8/SM) — finer placement
// granularity to smooth the wave tail. Same warps/SM, same SASS body.

static constexpr int T = 64;

__global__ void __launch_bounds__(64) lif_kernel(const float4* __restrict__ x,
                                                 float4* __restrict__ out,
                                                 int lanes4)  // B*N/4 per timestep
{
    int i = blockIdx.x * blockDim.x + threadIdx.x;
    if (i >= lanes4) return;

    float4 v = make_float4(0.f, 0.f, 0.f, 0.f);

    // distance-1 scalar prefetch
    float4 xt = __ldg(&x[i]);

    #pragma unroll 4
    for (int t = 0; t < T; ++t) {
        float4 xnext;
        if (t + 1 < T) xnext = __ldg(&x[(size_t)(t + 1) * lanes4 + i]);

        float4 h, s;
        h.x = v.x + (xt.x - v.x) * 0.5f;
        h.y = v.y + (xt.y - v.y) * 0.5f;
        h.z = v.z + (xt.z - v.z) * 0.5f;
        h.w = v.w + (xt.w - v.w) * 0.5f;

        s.x = (h.x >= 1.0f) ? 1.0f : 0.0f;
        s.y = (h.y >= 1.0f) ? 1.0f : 0.0f;
        s.z = (h.z >= 1.0f) ? 1.0f : 0.0f;
        s.w = (h.w >= 1.0f) ? 1.0f : 0.0f;

        v.x = (h.x >= 1.0f) ? 0.0f : h.x;
        v.y = (h.y >= 1.0f) ? 0.0f : h.y;
        v.z = (h.z >= 1.0f) ? 0.0f : h.z;
        v.w = (h.w >= 1.0f) ? 0.0f : h.w;

        out[(size_t)t * lanes4 + i] = s;

        xt = xnext;
    }
}

extern "C" void kernel_launch(void* const* d_in, const int* in_sizes, int n_in,
                              void* d_out, int out_size)
{
    const float4* x = (const float4*)d_in[0];
    float4* out = (float4*)d_out;

    int total = in_sizes[0];          // T * B * N
    int lanes = total / T;            // 524288
    int lanes4 = lanes / 4;           // 131072

    int threads = 64;                 // 2048 CTAs -> finest even balance
    int blocks = (lanes4 + threads - 1) / threads;
    lif_kernel<<<blocks, threads>>>(x, out, lanes4);
}

// round 12
// speedup vs baseline: 1.0007x; 1.0007x over previous
#include <cuda_runtime.h>
#include <cstdint>

// LIF recurrence: T=64 steps, B*N = 524288 independent lanes.
//   h = v + (x - v) * 0.5 ; s = (h>=1) ; v = s ? 0 : h
// Pure HBM stream: 134 MB in + 134 MB out (compulsory, zero reuse).
//
// FINAL — roofline reached. Eight isolated-lever experiments (vector
// width 8/16/32B, MLP depth 1-4, cache policy .cs/.nc both paths, R/W
// burst batching, CTA size 64/128/256) all measure 47.4-48.7us harness
// = ~5.65 TB/s sustained mixed-stream HBM3e. Compute pipes <20% busy.
// This is the exact best measured configuration (R6, 47.424us harness,
// 36.54us / 74.2% DRAM ncu): float4, distance-1 scalar prefetch,
// unroll 4, plain LDG.128/STG.128, 128-thread blocks (1024 CTAs,
// even per-SM balance).

static constexpr int T = 64;

__global__ void __launch_bounds__(128) lif_kernel(const float4* __restrict__ x,
                                                  float4* __restrict__ out,
                                                  int lanes4)  // B*N/4 per timestep
{
    int i = blockIdx.x * blockDim.x + threadIdx.x;
    if (i >= lanes4) return;

    float4 v = make_float4(0.f, 0.f, 0.f, 0.f);

    // distance-1 scalar prefetch
    float4 xt = x[i];

    #pragma unroll 4
    for (int t = 0; t < T; ++t) {
        float4 xnext;
        if (t + 1 < T) xnext = x[(size_t)(t + 1) * lanes4 + i];

        float4 h, s;
        h.x = v.x + (xt.x - v.x) * 0.5f;
        h.y = v.y + (xt.y - v.y) * 0.5f;
        h.z = v.z + (xt.z - v.z) * 0.5f;
        h.w = v.w + (xt.w - v.w) * 0.5f;

        s.x = (h.x >= 1.0f) ? 1.0f : 0.0f;
        s.y = (h.y >= 1.0f) ? 1.0f : 0.0f;
        s.z = (h.z >= 1.0f) ? 1.0f : 0.0f;
        s.w = (h.w >= 1.0f) ? 1.0f : 0.0f;

        v.x = (h.x >= 1.0f) ? 0.0f : h.x;
        v.y = (h.y >= 1.0f) ? 0.0f : h.y;
        v.z = (h.z >= 1.0f) ? 0.0f : h.z;
        v.w = (h.w >= 1.0f) ? 0.0f : h.w;

        out[(size_t)t * lanes4 + i] = s;

        xt = xnext;
    }
}

extern "C" void kernel_launch(void* const* d_in, const int* in_sizes, int n_in,
                              void* d_out, int out_size)
{
    const float4* x = (const float4*)d_in[0];
    float4* out = (float4*)d_out;

    int total = in_sizes[0];          // T * B * N
    int lanes = total / T;            // 524288
    int lanes4 = lanes / 4;           // 131072

    int threads = 128;                // 1024 CTAs -> even per-SM balance
    int blocks = (lanes4 + threads - 1) / threads;
    lif_kernel<<<blocks, threads>>>(x, out, lanes4);
}

// round 13
// speedup vs baseline: 1.0391x; 1.0384x over previous
#include <cuda_runtime.h>
#include <cstdint>

// LIF recurrence: T=64 steps, B*N = 524288 independent lanes.
//   h = v + (x - v) * 0.5 ; s = (h>=1) ; v = s ? 0 : h
// Pure HBM stream: 134 MB in + 134 MB out (compulsory, zero reuse).
//
// Roofline reached: nine isolated-lever experiments all measure
// 47.4-48.7us harness = ~5.65 TB/s sustained mixed-stream HBM3e.
// Winning structure (R6/R12): float4, distance-1 scalar prefetch,
// plain LDG.128/STG.128, 128-thread blocks (1024 CTAs, single wave,
// even per-SM balance).
// R13 delta (last clean knob): unroll 4 -> 8. Previous unroll-8 tests
// were confounded with __ldcs (R4) / array rotation (R8); this is the
// first clean sample. Wider ptxas scheduling window for LDG batching.

static constexpr int T = 64;

__global__ void __launch_bounds__(128) lif_kernel(const float4* __restrict__ x,
                                                  float4* __restrict__ out,
                                                  int lanes4)  // B*N/4 per timestep
{
    int i = blockIdx.x * blockDim.x + threadIdx.x;
    if (i >= lanes4) return;

    float4 v = make_float4(0.f, 0.f, 0.f, 0.f);

    // distance-1 scalar prefetch
    float4 xt = x[i];

    #pragma unroll 8
    for (int t = 0; t < T; ++t) {
        float4 xnext;
        if (t + 1 < T) xnext = x[(size_t)(t + 1) * lanes4 + i];

        float4 h, s;
        h.x = v.x + (xt.x - v.x) * 0.5f;
        h.y = v.y + (xt.y - v.y) * 0.5f;
        h.z = v.z + (xt.z - v.z) * 0.5f;
        h.w = v.w + (xt.w - v.w) * 0.5f;

        s.x = (h.x >= 1.0f) ? 1.0f : 0.0f;
        s.y = (h.y >= 1.0f) ? 1.0f : 0.0f;
        s.z = (h.z >= 1.0f) ? 1.0f : 0.0f;
        s.w = (h.w >= 1.0f) ? 1.0f : 0.0f;

        v.x = (h.x >= 1.0f) ? 0.0f : h.x;
        v.y = (h.y >= 1.0f) ? 0.0f : h.y;
        v.z = (h.z >= 1.0f) ? 0.0f : h.z;
        v.w = (h.w >= 1.0f) ? 0.0f : h.w;

        out[(size_t)t * lanes4 + i] = s;

        xt = xnext;
    }
}

extern "C" void kernel_launch(void* const* d_in, const int* in_sizes, int n_in,
                              void* d_out, int out_size)
{
    const float4* x = (const float4*)d_in[0];
    float4* out = (float4*)d_out;

    int total = in_sizes[0];          // T * B * N
    int lanes = total / T;            // 524288
    int lanes4 = lanes / 4;           // 131072

    int threads = 128;                // 1024 CTAs -> single wave, even balance
    int blocks = (lanes4 + threads - 1) / threads;
    lif_kernel<<<blocks, threads>>>(x, out, lanes4);
}